// round 5
// baseline (speedup 1.0000x reference)
#include <cuda_runtime.h>
#include <math.h>

typedef unsigned long long u64;
typedef unsigned int u32;

#define FMA2(d, a, b, c) \
    asm("fma.rn.f32x2 %0, %1, %2, %3;" : "=l"(d) : "l"(a), "l"(b), "l"(c))

__device__ __forceinline__ u64 pack2(float lo, float hi) {
    u64 r;
    asm("mov.b64 %0, {%1,%2};" : "=l"(r) : "f"(lo), "f"(hi));
    return r;
}
__device__ __forceinline__ float unpack_sum(u64 v) {
    float x, y;
    asm("mov.b64 {%0,%1}, %2;" : "=f"(x), "=f"(y) : "l"(v));
    return x + y;
}
__device__ __forceinline__ float my_tanh(float x) {
    float ax = fabsf(x);
    float e  = __expf(2.0f * ax);
    float r  = 1.0f - 2.0f / (e + 1.0f);
    return copysignf(r, x);
}

__device__ __forceinline__ u32 smem_u32(const void* p) {
    u32 a;
    asm("{ .reg .u64 t; cvta.to.shared.u64 t, %1; cvt.u32.u64 %0, t; }" : "=r"(a) : "l"(p));
    return a;
}

#define LDS128(v0, v1, addr) \
    asm volatile("ld.shared.v2.u64 {%0,%1}, [%2];" : "=l"(v0), "=l"(v1) : "r"(addr))
#define LDS64(v, addr) \
    asm volatile("ld.shared.u64 %0, [%1];" : "=l"(v) : "r"(addr))
#define STS64(addr, v) \
    asm volatile("st.shared.u64 [%0], %1;" :: "r"(addr), "l"(v))
#define STS32(addr, f) \
    asm volatile("st.shared.f32 [%0], %1;" :: "r"(addr), "f"(f))
#define LDS32(f, addr) \
    asm volatile("ld.shared.f32 %0, [%1];" : "=f"(f) : "r"(addr))

__device__ __forceinline__ void bulk_cp(u32 dst, const void* src, u32 bytes, u32 mbar) {
    asm volatile("cp.async.bulk.shared::cta.global.mbarrier::complete_tx::bytes [%0], [%1], %2, [%3];"
                 :: "r"(dst), "l"(src), "r"(bytes), "r"(mbar) : "memory");
}
__device__ __forceinline__ void expect_tx(u32 mbar, u32 bytes) {
    asm volatile("mbarrier.arrive.expect_tx.shared::cta.b64 _, [%0], %1;"
                 :: "r"(mbar), "r"(bytes) : "memory");
}
__device__ __forceinline__ void mbar_wait(u32 mbar, u32 parity) {
    asm volatile("{\n\t.reg .pred p;\nLW%=:\n\t"
                 "mbarrier.try_wait.parity.shared::cta.b64 p, [%0], %1;\n\t"
                 "@!p bra LW%=;\n\t}" :: "r"(mbar), "r"(parity) : "memory");
}

constexpr int BATCH = 4096;
constexpr int BC    = 32;      // batch rows per CTA (= lane)
constexpr int NT    = 256;     // 8 warps
constexpr int TPRE  = 64;
constexpr int TFWD  = 80;

// ---- smem layout (byte offsets) ----
constexpr u32 WBUF_SZ  = 49152;                 // per buffer: up to ih(16K)+hh(32K)
constexpr u32 OFF_WBUF = 0;                     // 2 buffers
constexpr u32 HS_SZ    = 128 * 33 * 8;          // 33792 ; hs[kpair][b] u64, pitch 33
constexpr u32 OFF_HS   = 2 * WBUF_SZ;           // 98304 ; double-buffered h
constexpr u32 OFF_XS   = OFF_HS + 2 * HS_SZ;    // 165888; xs[kpair][b], 64 rows
constexpr u32 OFF_YS   = OFF_XS + 64 * 33 * 8;  // 182784; ys[32][65] f32
constexpr u32 OFF_ENCB = OFF_YS + 32 * 65 * 4;  // 191104
constexpr u32 OFF_SSMB = OFF_ENCB + 1024;       // 192128
constexpr u32 OFF_CB   = OFF_SSMB + 1024;       // 193152
constexpr u32 OFF_MBAR = 193408;
constexpr u32 SMEM_TOTAL = 193536;

// Compute a 4-row j-tile over KCTOT k-chunks (32 kpairs each). First KCX chunks
// read xs (weight pitch wxp), the rest read h (pitch whp). Weights are smem
// broadcasts (LDS.128); h/x chunks are lane-consecutive LDS.64 cached in regs.
template <int KCX, int KCTOT>
__device__ __forceinline__ void chunk_mma(
    u32 wxa, int wxp, u32 wha, int whp,
    u32 xsa, u32 hsa, int lane8, u64 acc[4])
{
#pragma unroll 1
    for (int kc = 0; kc < KCTOT; kc++) {
        const bool isx = (KCX > 0) && (kc < KCX);
        u32 hb = (isx ? xsa + kc * 32 * 33 * 8
                      : hsa + (kc - KCX) * 32 * 33 * 8) + lane8;
        u64 hk[32];
#pragma unroll
        for (int i = 0; i < 32; i++) LDS64(hk[i], hb + i * 33 * 8);

        u32 wb = isx ? (wxa + kc * 256) : (wha + (kc - KCX) * 256);
        int wp = isx ? wxp : whp;
#pragma unroll
        for (int jj = 0; jj < 4; jj++) {
            u32 wr = wb + jj * wp;
#pragma unroll
            for (int kp = 0; kp < 32; kp += 2) {
                u64 w0, w1;
                LDS128(w0, w1, wr + kp * 8);
                FMA2(acc[jj], w0, hk[kp], acc[jj]);
                FMA2(acc[jj], w1, hk[kp + 1], acc[jj]);
            }
        }
    }
}

__global__ __launch_bounds__(NT, 1) void ss_fused(
    const float* __restrict__ pre_x, const float* __restrict__ pre_y,
    const float* __restrict__ fwd_x,
    const float* __restrict__ A_w, const float* __restrict__ A_b,
    const float* __restrict__ B_w, const float* __restrict__ B_b,
    const float* __restrict__ C_w, const float* __restrict__ C_b,
    const float* __restrict__ W_ih, const float* __restrict__ b_ih,
    const float* __restrict__ W_hh, const float* __restrict__ b_hh,
    float* __restrict__ out)
{
    extern __shared__ char smem[];
    const u32 SB = smem_u32(smem);
    const int tid = threadIdx.x, lane = tid & 31, warp = tid >> 5;
    const int lane8 = lane * 8;
    const int bbase = blockIdx.x * BC;

    // folded biases into smem
    {
        STS32(SB + OFF_ENCB + tid * 4, b_ih[tid] + b_hh[tid]);
        STS32(SB + OFF_SSMB + tid * 4, A_b[tid] + B_b[tid]);
        if (tid < 64) STS32(SB + OFF_CB + tid * 4, C_b[tid]);
    }
    // zero h buffer 0
    for (int i = tid; i < 128 * 33; i += NT) STS64(SB + OFF_HS + i * 8, 0ULL);
    if (tid == 0) {
        asm volatile("mbarrier.init.shared::cta.b64 [%0], 1;" :: "r"(SB + OFF_MBAR) : "memory");
        asm volatile("mbarrier.init.shared::cta.b64 [%0], 1;" :: "r"(SB + OFF_MBAR + 8) : "memory");
        asm volatile("fence.proxy.async.shared::cta;" ::: "memory");
    }
    __syncthreads();

    int cur = 0;
    u32 ph0 = 0, ph1 = 0;
#define BAR(b)  (SB + OFF_MBAR + (u32)(b) * 8)
#define WBA(b)  (SB + OFF_WBUF + (u32)(b) * WBUF_SZ)
#define WAIT_FLIP(b) do { if (b) { mbar_wait(BAR(1), ph1); ph1 ^= 1; } \
                          else   { mbar_wait(BAR(0), ph0); ph0 ^= 1; } } while (0)

    // ================= encoder =================
    for (int t = 0; t < TPRE; t++) {
        if (tid == 0) {
            expect_tx(BAR(0), 49152);
            bulk_cp(WBA(0), W_ih, 16384, BAR(0));
            bulk_cp(WBA(0) + 16384, W_hh, 32768, BAR(0));
        }
        // stage xy transposed: xs[kpair][b] (pairs 0..31 = x, 32..63 = y)
        const float* px = pre_x + ((size_t)t * BATCH + bbase) * 64;
        const float* py = pre_y + ((size_t)t * BATCH + bbase) * 64;
        for (int i = tid; i < 2048; i += NT) {
            int b = i >> 6, k = i & 63;
            STS32(SB + OFF_XS + ((u32)((k >> 1) * 33 + b) * 8) + (u32)(k & 1) * 4,
                  __ldg(&px[b * 64 + k]));
            STS32(SB + OFF_XS + ((u32)((32 + (k >> 1)) * 33 + b) * 8) + (u32)(k & 1) * 4,
                  __ldg(&py[b * 64 + k]));
        }
        __syncthreads();   // xs staged for all

        const u32 hcur = SB + OFF_HS + (u32)cur * HS_SZ;
        const u32 hnxt = SB + OFF_HS + (u32)(cur ^ 1) * HS_SZ;

        for (int c = 0; c < 8; c++) {
            const int cb = c & 1, nb = cb ^ 1;
            if (c < 7 && tid == 0) {
                expect_tx(BAR(nb), 49152);
                bulk_cp(WBA(nb), (const char*)W_ih + (c + 1) * 16384, 16384, BAR(nb));
                bulk_cp(WBA(nb) + 16384, (const char*)W_hh + (c + 1) * 32768, 32768, BAR(nb));
            }
            WAIT_FLIP(cb);

            u64 acc[4] = {0ULL, 0ULL, 0ULL, 0ULL};
            chunk_mma<2, 6>(WBA(cb) + (u32)(warp * 4) * 512, 512,
                            WBA(cb) + 16384 + (u32)(warp * 4) * 1024, 1024,
                            SB + OFF_XS, hcur, lane8, acc);

            const int j0 = c * 32 + warp * 4;
            float nh[4];
#pragma unroll
            for (int jj = 0; jj < 4; jj++) {
                float bs; LDS32(bs, SB + OFF_ENCB + (u32)(j0 + jj) * 4);
                nh[jj] = my_tanh(unpack_sum(acc[jj]) + bs);
            }
            const u32 r = hnxt + (u32)((j0 >> 1) * 33) * 8 + lane8;
            STS64(r, pack2(nh[0], nh[1]));
            STS64(r + 33 * 8, pack2(nh[2], nh[3]));
            __syncthreads();
        }
        cur ^= 1;
    }

    // ================= SSM rollout + output =================
    for (int t = 0; t < TFWD; t++) {
        if (tid == 0) {
            expect_tx(BAR(0), 40960);
            bulk_cp(WBA(0), B_w, 8192, BAR(0));
            bulk_cp(WBA(0) + 8192, A_w, 32768, BAR(0));
        }
        const float* fx = fwd_x + ((size_t)t * BATCH + bbase) * 64;
        for (int i = tid; i < 2048; i += NT) {
            int b = i >> 6, k = i & 63;
            STS32(SB + OFF_XS + ((u32)((k >> 1) * 33 + b) * 8) + (u32)(k & 1) * 4,
                  __ldg(&fx[b * 64 + k]));
        }
        __syncthreads();

        const u32 hcur = SB + OFF_HS + (u32)cur * HS_SZ;
        const u32 hnxt = SB + OFF_HS + (u32)(cur ^ 1) * HS_SZ;

        for (int c = 0; c < 8; c++) {
            const int cb = c & 1, nb = cb ^ 1;
            if (tid == 0) {
                if (c < 7) {
                    expect_tx(BAR(nb), 40960);
                    bulk_cp(WBA(nb), (const char*)B_w + (c + 1) * 8192, 8192, BAR(nb));
                    bulk_cp(WBA(nb) + 8192, (const char*)A_w + (c + 1) * 32768, 32768, BAR(nb));
                } else {
                    expect_tx(BAR(nb), 32768);     // C chunk 0
                    bulk_cp(WBA(nb), C_w, 32768, BAR(nb));
                }
            }
            WAIT_FLIP(cb);

            u64 acc[4] = {0ULL, 0ULL, 0ULL, 0ULL};
            chunk_mma<1, 5>(WBA(cb) + (u32)(warp * 4) * 256, 256,
                            WBA(cb) + 8192 + (u32)(warp * 4) * 1024, 1024,
                            SB + OFF_XS, hcur, lane8, acc);

            const int j0 = c * 32 + warp * 4;
            float nh[4];
#pragma unroll
            for (int jj = 0; jj < 4; jj++) {
                float bs; LDS32(bs, SB + OFF_SSMB + (u32)(j0 + jj) * 4);
                nh[jj] = unpack_sum(acc[jj]) + bs;
            }
            const u32 r = hnxt + (u32)((j0 >> 1) * 33) * 8 + lane8;
            STS64(r, pack2(nh[0], nh[1]));
            STS64(r + 33 * 8, pack2(nh[2], nh[3]));
            __syncthreads();
        }

        // output projection: y = C * h_new + C_b  (2 chunks of 32 o-rows)
        for (int cc = 0; cc < 2; cc++) {
            const int c = 8 + cc, cb = c & 1, nb = cb ^ 1;
            if (cc == 0 && tid == 0) {
                expect_tx(BAR(nb), 32768);         // C chunk 1
                bulk_cp(WBA(nb), (const char*)C_w + 32768, 32768, BAR(nb));
            }
            WAIT_FLIP(cb);

            u64 acc[4] = {0ULL, 0ULL, 0ULL, 0ULL};
            chunk_mma<0, 4>(0, 0, WBA(cb) + (u32)(warp * 4) * 1024, 1024,
                            0, hnxt, lane8, acc);

            const int o0 = cc * 32 + warp * 4;
#pragma unroll
            for (int jj = 0; jj < 4; jj++) {
                float bs; LDS32(bs, SB + OFF_CB + (u32)(o0 + jj) * 4);
                STS32(SB + OFF_YS + (u32)(lane * 65 + o0 + jj) * 4,
                      unpack_sum(acc[jj]) + bs);
            }
            __syncthreads();
        }

        // stream y tile to gmem, coalesced
        float* op = out + ((size_t)t * BATCH + bbase) * 64;
        for (int i = tid; i < 2048; i += NT) {
            int b = i >> 6, o = i & 63;
            float v; LDS32(v, SB + OFF_YS + (u32)(b * 65 + o) * 4);
            op[b * 64 + o] = v;
        }
        cur ^= 1;
    }
#undef BAR
#undef WBA
#undef WAIT_FLIP
}

extern "C" void kernel_launch(void* const* d_in, const int* in_sizes, int n_in,
                              void* d_out, int out_size) {
    const float* pre_x = (const float*)d_in[0];
    const float* pre_y = (const float*)d_in[1];
    const float* fwd_x = (const float*)d_in[2];
    const float* A_w   = (const float*)d_in[3];
    const float* A_b   = (const float*)d_in[4];
    const float* B_w   = (const float*)d_in[5];
    const float* B_b   = (const float*)d_in[6];
    const float* C_w   = (const float*)d_in[7];
    const float* C_b   = (const float*)d_in[8];
    const float* W_ih  = (const float*)d_in[9];
    const float* b_ih  = (const float*)d_in[10];
    const float* W_hh  = (const float*)d_in[11];
    const float* b_hh  = (const float*)d_in[12];
    float* out = (float*)d_out;

    cudaFuncSetAttribute(ss_fused, cudaFuncAttributeMaxDynamicSharedMemorySize,
                         SMEM_TOTAL);
    ss_fused<<<BATCH / BC, NT, SMEM_TOTAL>>>(pre_x, pre_y, fwd_x, A_w, A_b,
                                             B_w, B_b, C_w, C_b, W_ih, b_ih,
                                             W_hh, b_hh, out);
}

// round 7
// speedup vs baseline: 4.3563x; 4.3563x over previous
#include <cuda_runtime.h>
#include <cuda_bf16.h>
#include <math.h>

typedef unsigned long long u64;
typedef unsigned int u32;
typedef unsigned short u16;

// -------- prepped fragment-order weight streams (written by prep kernel) --------
__device__ __align__(128) unsigned char g_enc[589824];  // 18 chunks x 32KB, Ktilde=1152
__device__ __align__(128) unsigned char g_ssm[491520];  // 15 chunks x 32KB, Ktilde=960
__device__ __align__(128) unsigned char g_cw[98304];    //  3 chunks x 32KB, 48 slabs

__device__ __forceinline__ u16 bf_hi(float w) { return __bfloat16_as_ushort(__float2bfloat16(w)); }
__device__ __forceinline__ u16 bf_lo(float w) {
    float h = __bfloat162float(__float2bfloat16(w));
    return __bfloat16_as_ushort(__float2bfloat16(w - h));
}

// One thread per output bf16. Layout: chunk(32KB) -> slab(8KB enc/ssm, 2KB C) ->
// block(512B, (warp,mtile)) -> lane(16B) -> 4 regs x bf16x2, matching the PTX
// m16n8k16 A-fragment: reg r holds (row + (r&1)*8, k + (r>>1)*8 + h).
__global__ void prep(const float* __restrict__ A_w, const float* __restrict__ B_w,
                     const float* __restrict__ C_w, const float* __restrict__ W_ih,
                     const float* __restrict__ W_hh) {
    u32 e = blockIdx.x * 256u + threadIdx.x;
    u32 kind, pos;
    if (e < 294912u)      { kind = 0; pos = e * 2u; }
    else if (e < 540672u) { kind = 1; pos = (e - 294912u) * 2u; }
    else if (e < 589824u) { kind = 2; pos = (e - 540672u) * 2u; }
    else return;
    u32 chunk = pos >> 15, inch = pos & 32767u;
    u32 slab, w, m, r3;
    if (kind < 2) { slab = inch >> 13; u32 r2 = inch & 8191u; u32 blk = r2 >> 9; w = blk >> 1; m = blk & 1u; r3 = r2 & 511u; }
    else          { slab = inch >> 11; u32 r2 = inch & 2047u; w = r2 >> 9; m = 0; r3 = r2 & 511u; }
    u32 t = r3 >> 4, r4 = r3 & 15u, reg = r4 >> 2, h = (r4 & 3u) >> 1;
    u32 row = (t >> 2) + (reg & 1u) * 8u;
    u32 kl  = (t & 3u) * 2u + (reg >> 1) * 8u + h;
    float src; u32 p;
    if (kind == 0) {
        u32 j = w * 32u + m * 16u + row;
        u32 kt = (chunk * 4u + slab) * 16u + kl;
        p = kt / 384u; u32 kk = kt % 384u;
        src = (kk < 128u) ? W_ih[j * 128u + kk] : W_hh[j * 256u + kk - 128u];
        *(u16*)(g_enc + pos) = (p == 1u) ? bf_lo(src) : bf_hi(src);
    } else if (kind == 1) {
        u32 j = w * 32u + m * 16u + row;
        u32 kt = (chunk * 4u + slab) * 16u + kl;
        p = kt / 320u; u32 kk = kt % 320u;
        src = (kk < 64u) ? B_w[j * 64u + kk] : A_w[j * 256u + kk - 64u];
        *(u16*)(g_ssm + pos) = (p == 1u) ? bf_lo(src) : bf_hi(src);
    } else {
        u32 o = w * 16u + row;
        u32 g4 = chunk * 16u + slab;
        p = g4 >> 4;
        u32 su = p * 20u + 4u + (g4 & 15u);          // U h-region slabs only
        u32 k  = su * 16u + kl - (p * 320u + 64u);
        src = C_w[o * 256u + k];
        *(u16*)(g_cw + pos) = (p == 1u) ? bf_lo(src) : bf_hi(src);
    }
}

// ---------------- PTX helpers ----------------
__device__ __forceinline__ u32 smem_u32(const void* p) {
    u32 a;
    asm("{ .reg .u64 t; cvta.to.shared.u64 t, %1; cvt.u32.u64 %0, t; }" : "=r"(a) : "l"(p));
    return a;
}
#define STS16(addr, v)  asm volatile("st.shared.u16 [%0], %1;" :: "r"(addr), "h"(v))
#define STS32(addr, f)  asm volatile("st.shared.f32 [%0], %1;" :: "r"(addr), "f"(f))
#define LDS128U(r, addr) \
    asm volatile("ld.shared.v4.u32 {%0,%1,%2,%3}, [%4];" \
                 : "=r"((r)[0]), "=r"((r)[1]), "=r"((r)[2]), "=r"((r)[3]) : "r"(addr))
#define LDS32U(r, addr) asm volatile("ld.shared.u32 %0, [%1];" : "=r"(r) : "r"(addr))

#define MMA16816(c, a, b0, b1) \
    asm volatile("mma.sync.aligned.m16n8k16.row.col.f32.bf16.bf16.f32 " \
                 "{%0,%1,%2,%3},{%4,%5,%6,%7},{%8,%9},{%0,%1,%2,%3};" \
                 : "+f"((c)[0]), "+f"((c)[1]), "+f"((c)[2]), "+f"((c)[3]) \
                 : "r"((a)[0]), "r"((a)[1]), "r"((a)[2]), "r"((a)[3]), "r"(b0), "r"(b1))

__device__ __forceinline__ void bulk_cp(u32 dst, const void* src, u32 bytes, u32 mbar) {
    asm volatile("cp.async.bulk.shared::cta.global.mbarrier::complete_tx::bytes [%0], [%1], %2, [%3];"
                 :: "r"(dst), "l"(src), "r"(bytes), "r"(mbar) : "memory");
}
__device__ __forceinline__ void expect_tx(u32 mbar, u32 bytes) {
    asm volatile("mbarrier.arrive.expect_tx.shared::cta.b64 _, [%0], %1;"
                 :: "r"(mbar), "r"(bytes) : "memory");
}
__device__ __forceinline__ void mbar_init(u32 mbar, u32 cnt) {
    asm volatile("mbarrier.init.shared::cta.b64 [%0], %1;" :: "r"(mbar), "r"(cnt) : "memory");
}
__device__ __forceinline__ void mbar_arrive(u32 mbar) {
    asm volatile("mbarrier.arrive.shared::cta.b64 _, [%0];" :: "r"(mbar) : "memory");
}
__device__ __forceinline__ void mbar_wait(u32 mbar, u32 parity) {
    asm volatile("{\n\t.reg .pred p;\nLW%=:\n\t"
                 "mbarrier.try_wait.parity.acquire.cta.shared::cta.b64 p, [%0], %1;\n\t"
                 "@!p bra LW%=;\n\t}" :: "r"(mbar), "r"(parity) : "memory");
}
#define BAR1() asm volatile("bar.sync 1, 256;" ::: "memory")

__device__ __forceinline__ float my_tanh(float x) {
    float ax = fabsf(x);
    float e  = __expf(2.0f * ax);
    float r  = 1.0f - 2.0f / (e + 1.0f);
    return copysignf(r, x);
}
__device__ __forceinline__ void bsplit(float v, u16& hi, u16& lo) {
    __nv_bfloat16 hb = __float2bfloat16(v);
    hi = __bfloat16_as_ushort(hb);
    lo = __bfloat16_as_ushort(__float2bfloat16(v - __bfloat162float(hb)));
}

// ---------------- smem layout ----------------
constexpr u32 UP        = 2320;         // U row pitch bytes (conflict-free for frag reads)
constexpr u32 OFF_RING  = 0;            // 4 x 32768
constexpr u32 OFF_U     = 131072;       // 32 x 2320 = 74240
constexpr u32 OFF_FULL  = 205312;       // 4 x 8
constexpr u32 OFF_EMPTY = 205344;       // 4 x 8
constexpr u32 SMEM_TOTAL = 205440;

// triple-slot U write: hi at k, hi at k+P, lo at k+2P (P in elements; bytes 2P)
__device__ __forceinline__ void put_trip(u32 ub, u32 k, float v, u32 Pb) {
    u16 hi, lo; bsplit(v, hi, lo);
    u32 a = ub + k * 2u;
    STS16(a, hi); STS16(a + Pb, hi); STS16(a + 2u * Pb, lo);
}

// main GEMM over nch 32KB chunks (4 slabs each): D[256,32] += Ahat * U^T
__device__ __forceinline__ void gemm_main(u32 SB, int warp, int lane, int nch,
                                          int& gch, float acc[2][4][4]) {
    const u32 bB = SB + OFF_U + (u32)(lane >> 2) * UP + (u32)(lane & 3) * 4u;
    u32 kt = 0;
    for (int c = 0; c < nch; c++) {
        int slot = gch & 3;
        mbar_wait(SB + OFF_FULL + (u32)slot * 8u, (gch >> 2) & 1);
        u32 ab = SB + OFF_RING + (u32)slot * 32768u + (u32)(warp * 1024) + (u32)(lane * 16);
#pragma unroll
        for (int sl = 0; sl < 4; sl++) {
            u32 a0[4], a1[4];
            LDS128U(a0, ab);
            LDS128U(a1, ab + 512u);
            ab += 8192u;
            u32 bk = bB + kt * 2u;
            u32 b0[4], b1[4];
#pragma unroll
            for (int nt = 0; nt < 4; nt++) {
                LDS32U(b0[nt], bk + (u32)nt * (8u * UP));
                LDS32U(b1[nt], bk + (u32)nt * (8u * UP) + 16u);
            }
#pragma unroll
            for (int nt = 0; nt < 4; nt++) {
                MMA16816(acc[0][nt], a0, b0[nt], b1[nt]);
                MMA16816(acc[1][nt], a1, b0[nt], b1[nt]);
            }
            kt += 16;
        }
        __syncwarp();
        if (lane == 0) mbar_arrive(SB + OFF_EMPTY + (u32)slot * 8u);
        gch++;
    }
}

__global__ __launch_bounds__(288, 1) void ss_main(
    const float* __restrict__ pre_x, const float* __restrict__ pre_y,
    const float* __restrict__ fwd_x,
    const float* __restrict__ A_b, const float* __restrict__ B_b,
    const float* __restrict__ C_b, const float* __restrict__ b_ih,
    const float* __restrict__ b_hh, float* __restrict__ out)
{
    extern __shared__ char smraw[];
    const u32 SB = smem_u32(smraw);
    const int tid = threadIdx.x, lane = tid & 31, warp = tid >> 5;
    const int bbase = blockIdx.x * 32;

    if (tid == 0) {
        for (int s = 0; s < 4; s++) {
            mbar_init(SB + OFF_FULL + s * 8, 1);
            mbar_init(SB + OFF_EMPTY + s * 8, 8);
        }
        asm volatile("fence.proxy.async.shared::cta;" ::: "memory");
    }
    if (warp < 8) {
        // zero entire U
        for (int i = tid; i < (int)(32 * UP / 4); i += 256) STS32(SB + OFF_U + (u32)i * 4u, 0.0f);
        // stage x0,y0 (enc layout: x at k 0..63, y at 64..127; parts 0/384/768)
        {
            int b = tid >> 3, k16 = (tid & 7) * 16;
            const float* s = ((k16 < 64) ? pre_x : pre_y) + (size_t)(bbase + b) * 64 + (k16 & 63);
            u32 ub = SB + OFF_U + (u32)b * UP;
#pragma unroll
            for (int kk = 0; kk < 16; kk++)
                put_trip(ub, (u32)(k16 + kk), s[kk], 768u);
        }
    }
    __syncthreads();   // all 288: mbarriers + U visible; producer starts

    // ---------------- producer (warp 8, lane 0) ----------------
    if (warp == 8) {
        if (lane == 0) {
            int pg = 0;
            auto push = [&](const unsigned char* src) {
                int slot = pg & 3;
                if (pg >= 4) mbar_wait(SB + OFF_EMPTY + (u32)slot * 8u, ((pg >> 2) - 1) & 1);
                expect_tx(SB + OFF_FULL + (u32)slot * 8u, 32768u);
                bulk_cp(SB + OFF_RING + (u32)slot * 32768u, src, 32768u, SB + OFF_FULL + (u32)slot * 8u);
                pg++;
            };
            for (int t = 0; t < 64; t++)
                for (int c = 0; c < 18; c++) push(g_enc + (size_t)c * 32768);
            for (int t = 0; t < 80; t++) {
                for (int c = 0; c < 15; c++) push(g_ssm + (size_t)c * 32768);
                for (int c = 0; c < 3; c++)  push(g_cw + (size_t)c * 32768);
            }
        }
        return;
    }

    // ---------------- compute warps 0..7 ----------------
    const int gg = lane >> 2, tig = lane & 3;
    float ebias[4], sbias[4], cb[2];
#pragma unroll
    for (int m = 0; m < 2; m++)
#pragma unroll
        for (int rh = 0; rh < 2; rh++) {
            int j = warp * 32 + m * 16 + gg + rh * 8;
            ebias[m * 2 + rh] = b_ih[j] + b_hh[j];
            sbias[m * 2 + rh] = A_b[j] + B_b[j];
        }
    if (warp < 4) { cb[0] = C_b[warp * 16 + gg]; cb[1] = C_b[warp * 16 + gg + 8]; }

    int gch = 0;

    // ================= encoder =================
    for (int t = 0; t < 64; t++) {
        BAR1();
        float acc[2][4][4] = {};
        gemm_main(SB, warp, lane, 18, gch, acc);
        BAR1();
        const bool last = (t == 63);
        const u32 hb = last ? 64u : 128u;      // h base slot in U (ssm vs enc layout)
        const u32 Pb = last ? 640u : 768u;     // part stride bytes
#pragma unroll
        for (int m = 0; m < 2; m++)
#pragma unroll
            for (int nt = 0; nt < 4; nt++)
#pragma unroll
                for (int r = 0; r < 4; r++) {
                    int j = warp * 32 + m * 16 + gg + (r >> 1) * 8;
                    int b = nt * 8 + tig * 2 + (r & 1);
                    float v = my_tanh(acc[m][nt][r] + ebias[m * 2 + (r >> 1)]);
                    put_trip(SB + OFF_U + (u32)b * UP, hb + (u32)j, v, Pb);
                }
        // stage next inputs
        if (!last) {
            int b = tid >> 3, k16 = (tid & 7) * 16;
            const float* s = ((k16 < 64) ? pre_x : pre_y) +
                             (size_t)(t + 1) * 4096 * 64 + (size_t)(bbase + b) * 64 + (k16 & 63);
            u32 ub = SB + OFF_U + (u32)b * UP;
#pragma unroll
            for (int kk = 0; kk < 16; kk++)
                put_trip(ub, (u32)(k16 + kk), s[kk], 768u);
        } else {
            int b = tid >> 3, k16 = (tid & 7) * 16;
            if (k16 < 64) {
                const float* s = fwd_x + (size_t)(bbase + b) * 64 + k16;
                u32 ub = SB + OFF_U + (u32)b * UP;
#pragma unroll
                for (int kk = 0; kk < 16; kk++)
                    put_trip(ub, (u32)(k16 + kk), s[kk], 640u);
            }
        }
    }

    // ================= SSM + output projection =================
    for (int t = 0; t < 80; t++) {
        BAR1();
        float acc[2][4][4] = {};
        gemm_main(SB, warp, lane, 15, gch, acc);
        BAR1();
        // write h_t (ssm layout: h at 64.., parts 0/320/640)
#pragma unroll
        for (int m = 0; m < 2; m++)
#pragma unroll
            for (int nt = 0; nt < 4; nt++)
#pragma unroll
                for (int r = 0; r < 4; r++) {
                    int j = warp * 32 + m * 16 + gg + (r >> 1) * 8;
                    int b = nt * 8 + tig * 2 + (r & 1);
                    float v = acc[m][nt][r] + sbias[m * 2 + (r >> 1)];
                    put_trip(SB + OFF_U + (u32)b * UP, 64u + (u32)j, v, 640u);
                }
        BAR1();
        // phase 3: warps 0-3 run C projection; warps 4-7 stage x_{t+1} and release chunks
        if (warp < 4) {
            float accc[4][4] = {};
            const u32 bB = SB + OFF_U + (u32)(lane >> 2) * UP + (u32)(lane & 3) * 4u;
            for (int c = 0; c < 3; c++) {
                int slot = gch & 3;
                mbar_wait(SB + OFF_FULL + (u32)slot * 8u, (gch >> 2) & 1);
                u32 ab = SB + OFF_RING + (u32)slot * 32768u + (u32)(warp * 512) + (u32)(lane * 16);
#pragma unroll 4
                for (int sl = 0; sl < 16; sl++) {
                    u32 su = (u32)c * 20u + 4u + (u32)sl;
                    u32 a0[4];
                    LDS128U(a0, ab + (u32)sl * 2048u);
                    u32 bk = bB + su * 32u;
#pragma unroll
                    for (int nt = 0; nt < 4; nt++) {
                        u32 b0, b1;
                        LDS32U(b0, bk + (u32)nt * (8u * UP));
                        LDS32U(b1, bk + (u32)nt * (8u * UP) + 16u);
                        MMA16816(accc[nt], a0, b0, b1);
                    }
                }
                __syncwarp();
                if (lane == 0) mbar_arrive(SB + OFF_EMPTY + (u32)slot * 8u);
                gch++;
            }
            // epilogue: y -> gmem
            float* op = out + (size_t)t * 4096 * 64 + (size_t)bbase * 64;
#pragma unroll
            for (int nt = 0; nt < 4; nt++)
#pragma unroll
                for (int r = 0; r < 4; r++) {
                    int o = warp * 16 + gg + (r >> 1) * 8;
                    int b = nt * 8 + tig * 2 + (r & 1);
                    op[(size_t)b * 64 + o] = accc[nt][r] + cb[r >> 1];
                }
        } else {
            if (t < 79) {
                int idx = tid - 128;
                int b = idx >> 2, k16 = (idx & 3) * 16;
                const float* s = fwd_x + (size_t)(t + 1) * 4096 * 64 + (size_t)(bbase + b) * 64 + k16;
                u32 ub = SB + OFF_U + (u32)b * UP;
#pragma unroll
                for (int kk = 0; kk < 16; kk++)
                    put_trip(ub, (u32)(k16 + kk), s[kk], 640u);
            }
            for (int c = 0; c < 3; c++) {
                int slot = gch & 3;
                __syncwarp();
                if (lane == 0) mbar_arrive(SB + OFF_EMPTY + (u32)slot * 8u);
                gch++;
            }
        }
    }
}

extern "C" void kernel_launch(void* const* d_in, const int* in_sizes, int n_in,
                              void* d_out, int out_size) {
    const float* pre_x = (const float*)d_in[0];
    const float* pre_y = (const float*)d_in[1];
    const float* fwd_x = (const float*)d_in[2];
    const float* A_w   = (const float*)d_in[3];
    const float* A_b   = (const float*)d_in[4];
    const float* B_w   = (const float*)d_in[5];
    const float* B_b   = (const float*)d_in[6];
    const float* C_w   = (const float*)d_in[7];
    const float* C_b   = (const float*)d_in[8];
    const float* W_ih  = (const float*)d_in[9];
    const float* b_ih  = (const float*)d_in[10];
    const float* W_hh  = (const float*)d_in[11];
    const float* b_hh  = (const float*)d_in[12];
    float* out = (float*)d_out;

    prep<<<2304, 256>>>(A_w, B_w, C_w, W_ih, W_hh);
    cudaFuncSetAttribute(ss_main, cudaFuncAttributeMaxDynamicSharedMemorySize, SMEM_TOTAL);
    ss_main<<<128, 288, SMEM_TOTAL>>>(pre_x, pre_y, fwd_x, A_b, B_b, C_b,
                                      b_ih, b_hh, out);
}

// round 8
// speedup vs baseline: 5.8186x; 1.3357x over previous
#include <cuda_runtime.h>
#include <cuda_fp16.h>
#include <math.h>

typedef unsigned long long u64;
typedef unsigned int u32;
typedef unsigned short u16;

// -------- prepped fragment-order weight streams (fp16 hi/lo, 2-term split) --------
__device__ __align__(128) unsigned char g_enc[393216];  // 12 chunks x 32KB, Ktilde=768
__device__ __align__(128) unsigned char g_ssm[327680];  // 10 chunks x 32KB, Ktilde=640
__device__ __align__(128) unsigned char g_cw[65536];    //  2 chunks x 32KB, Ktilde=512

__device__ __forceinline__ u16 hf_hi(float w) { return __half_as_ushort(__float2half_rn(w)); }
__device__ __forceinline__ u16 hf_lo(float w) {
    float h = __half2float(__float2half_rn(w));
    return __half_as_ushort(__float2half_rn(w - h));
}

// One thread per output fp16. Layout: chunk(32KB) -> slab(8KB enc/ssm, 2KB C) ->
// block(512B, (warp,mtile)) -> lane(16B) -> 4 regs x f16x2, matching the PTX
// m16n8k16 A-fragment: reg r holds (row + (r&1)*8, k + (r>>1)*8 + h).
__global__ void prep(const float* __restrict__ A_w, const float* __restrict__ B_w,
                     const float* __restrict__ C_w, const float* __restrict__ W_ih,
                     const float* __restrict__ W_hh) {
    u32 e = blockIdx.x * 256u + threadIdx.x;
    u32 kind, pos;
    if (e < 196608u)      { kind = 0; pos = e * 2u; }
    else if (e < 360448u) { kind = 1; pos = (e - 196608u) * 2u; }
    else if (e < 393216u) { kind = 2; pos = (e - 360448u) * 2u; }
    else return;
    u32 chunk = pos >> 15, inch = pos & 32767u;
    u32 slab, w, m, r3;
    if (kind < 2) { slab = inch >> 13; u32 r2 = inch & 8191u; u32 blk = r2 >> 9; w = blk >> 1; m = blk & 1u; r3 = r2 & 511u; }
    else          { slab = inch >> 11; u32 r2 = inch & 2047u; w = r2 >> 9; m = 0; r3 = r2 & 511u; }
    u32 t = r3 >> 4, r4 = r3 & 15u, reg = r4 >> 2, h = (r4 & 3u) >> 1;
    u32 row = (t >> 2) + (reg & 1u) * 8u;
    u32 kl  = (t & 3u) * 2u + (reg >> 1) * 8u + h;
    float src; u32 p;
    if (kind == 0) {
        u32 j = w * 32u + m * 16u + row;
        u32 kt = (chunk * 4u + slab) * 16u + kl;
        p = kt / 384u; u32 kk = kt % 384u;
        src = (kk < 128u) ? W_ih[j * 128u + kk] : W_hh[j * 256u + kk - 128u];
        *(u16*)(g_enc + pos) = p ? hf_lo(src) : hf_hi(src);
    } else if (kind == 1) {
        u32 j = w * 32u + m * 16u + row;
        u32 kt = (chunk * 4u + slab) * 16u + kl;
        p = kt / 320u; u32 kk = kt % 320u;
        src = (kk < 64u) ? B_w[j * 64u + kk] : A_w[j * 256u + kk - 64u];
        *(u16*)(g_ssm + pos) = p ? hf_lo(src) : hf_hi(src);
    } else {
        u32 o = w * 16u + row;
        u32 g4 = chunk * 16u + slab;
        p = g4 >> 4;
        u32 k = (g4 & 15u) * 16u + kl;        // 0..255
        src = C_w[o * 256u + k];
        *(u16*)(g_cw + pos) = p ? hf_lo(src) : hf_hi(src);
    }
}

// ---------------- PTX helpers ----------------
__device__ __forceinline__ u32 smem_u32(const void* p) {
    u32 a;
    asm("{ .reg .u64 t; cvta.to.shared.u64 t, %1; cvt.u32.u64 %0, t; }" : "=r"(a) : "l"(p));
    return a;
}
#define STS16(addr, v)  asm volatile("st.shared.u16 [%0], %1;" :: "r"(addr), "h"(v))
#define STS32(addr, f)  asm volatile("st.shared.f32 [%0], %1;" :: "r"(addr), "f"(f))
#define LDS128U(r, addr) \
    asm volatile("ld.shared.v4.u32 {%0,%1,%2,%3}, [%4];" \
                 : "=r"((r)[0]), "=r"((r)[1]), "=r"((r)[2]), "=r"((r)[3]) : "r"(addr))
#define LDS32U(r, addr) asm volatile("ld.shared.u32 %0, [%1];" : "=r"(r) : "r"(addr))

#define MMA16816(c, a, b0, b1) \
    asm volatile("mma.sync.aligned.m16n8k16.row.col.f32.f16.f16.f32 " \
                 "{%0,%1,%2,%3},{%4,%5,%6,%7},{%8,%9},{%0,%1,%2,%3};" \
                 : "+f"((c)[0]), "+f"((c)[1]), "+f"((c)[2]), "+f"((c)[3]) \
                 : "r"((a)[0]), "r"((a)[1]), "r"((a)[2]), "r"((a)[3]), "r"(b0), "r"(b1))

__device__ __forceinline__ void bulk_cp(u32 dst, const void* src, u32 bytes, u32 mbar) {
    asm volatile("cp.async.bulk.shared::cta.global.mbarrier::complete_tx::bytes [%0], [%1], %2, [%3];"
                 :: "r"(dst), "l"(src), "r"(bytes), "r"(mbar) : "memory");
}
__device__ __forceinline__ void expect_tx(u32 mbar, u32 bytes) {
    asm volatile("mbarrier.arrive.expect_tx.shared::cta.b64 _, [%0], %1;"
                 :: "r"(mbar), "r"(bytes) : "memory");
}
__device__ __forceinline__ void mbar_init(u32 mbar, u32 cnt) {
    asm volatile("mbarrier.init.shared::cta.b64 [%0], %1;" :: "r"(mbar), "r"(cnt) : "memory");
}
__device__ __forceinline__ void mbar_arrive(u32 mbar) {
    asm volatile("mbarrier.arrive.shared::cta.b64 _, [%0];" :: "r"(mbar) : "memory");
}
__device__ __forceinline__ void mbar_wait(u32 mbar, u32 parity) {
    asm volatile("{\n\t.reg .pred p;\nLW%=:\n\t"
                 "mbarrier.try_wait.parity.acquire.cta.shared::cta.b64 p, [%0], %1;\n\t"
                 "@!p bra LW%=;\n\t}" :: "r"(mbar), "r"(parity) : "memory");
}
#define BAR1() asm volatile("bar.sync 1, 256;" ::: "memory")

__device__ __forceinline__ float my_tanh(float x) {
    float ax = fabsf(x);
    float e  = __expf(2.0f * ax);
    float r  = 1.0f - 2.0f / (e + 1.0f);
    return copysignf(r, x);
}

// ---------------- smem layout ----------------
constexpr u32 UP        = 1552;         // U row pitch bytes (UP % 128 == 16 -> conflict-free)
constexpr u32 OFF_RING  = 0;            // 4 x 32768
constexpr u32 OFF_U     = 131072;       // 32 x 1552 = 49664
constexpr u32 OFF_FULL  = 180736;       // 4 x 8
constexpr u32 OFF_EMPTY = 180768;       // 4 x 8
constexpr u32 SMEM_TOTAL = 180800;

// dual-slot U write: hi at k, lo at k+P (Pb = part stride bytes)
__device__ __forceinline__ void put_duo(u32 ub, u32 k, float v, u32 Pb) {
    __half hb = __float2half_rn(v);
    u16 hi = __half_as_ushort(hb);
    u16 lo = __half_as_ushort(__float2half_rn(v - __half2float(hb)));
    u32 a = ub + k * 2u;
    STS16(a, hi); STS16(a + Pb, lo);
}

// main GEMM over nch 32KB chunks (4 slabs each): D[256,32] += Ahat * U^T
__device__ __forceinline__ void gemm_main(u32 SB, int warp, int lane, int nch,
                                          int& gch, float acc[2][4][4]) {
    const u32 bB = SB + OFF_U + (u32)(lane >> 2) * UP + (u32)(lane & 3) * 4u;
    u32 kt = 0;
    for (int c = 0; c < nch; c++) {
        int slot = gch & 3;
        mbar_wait(SB + OFF_FULL + (u32)slot * 8u, (gch >> 2) & 1);
        u32 ab = SB + OFF_RING + (u32)slot * 32768u + (u32)(warp * 1024) + (u32)(lane * 16);
#pragma unroll
        for (int sl = 0; sl < 4; sl++) {
            u32 a0[4], a1[4];
            LDS128U(a0, ab);
            LDS128U(a1, ab + 512u);
            ab += 8192u;
            u32 bk = bB + kt * 2u;
            u32 b0[4], b1[4];
#pragma unroll
            for (int nt = 0; nt < 4; nt++) {
                LDS32U(b0[nt], bk + (u32)nt * (8u * UP));
                LDS32U(b1[nt], bk + (u32)nt * (8u * UP) + 16u);
            }
#pragma unroll
            for (int nt = 0; nt < 4; nt++) {
                MMA16816(acc[0][nt], a0, b0[nt], b1[nt]);
                MMA16816(acc[1][nt], a1, b0[nt], b1[nt]);
            }
            kt += 16;
        }
        __syncwarp();
        if (lane == 0) mbar_arrive(SB + OFF_EMPTY + (u32)slot * 8u);
        gch++;
    }
}

__global__ __launch_bounds__(288, 1) void ss_main(
    const float* __restrict__ pre_x, const float* __restrict__ pre_y,
    const float* __restrict__ fwd_x,
    const float* __restrict__ A_b, const float* __restrict__ B_b,
    const float* __restrict__ C_b, const float* __restrict__ b_ih,
    const float* __restrict__ b_hh, float* __restrict__ out)
{
    extern __shared__ char smraw[];
    const u32 SB = smem_u32(smraw);
    const int tid = threadIdx.x, lane = tid & 31, warp = tid >> 5;
    const int bbase = blockIdx.x * 32;

    if (tid == 0) {
        for (int s = 0; s < 4; s++) {
            mbar_init(SB + OFF_FULL + s * 8, 1);
            mbar_init(SB + OFF_EMPTY + s * 8, 8);
        }
        asm volatile("fence.proxy.async.shared::cta;" ::: "memory");
    }
    if (warp < 8) {
        // zero entire U
        for (int i = tid; i < (int)(32 * UP / 4); i += 256) STS32(SB + OFF_U + (u32)i * 4u, 0.0f);
        // stage x0,y0 (enc layout: x at k 0..63, y at 64..127; parts 0/384)
        {
            int b = tid >> 3, k16 = (tid & 7) * 16;
            const float* s = ((k16 < 64) ? pre_x : pre_y) + (size_t)(bbase + b) * 64 + (k16 & 63);
            u32 ub = SB + OFF_U + (u32)b * UP;
#pragma unroll
            for (int kk = 0; kk < 16; kk++)
                put_duo(ub, (u32)(k16 + kk), s[kk], 768u);
        }
    }
    __syncthreads();   // all 288: mbarriers + U visible; producer starts

    // ---------------- producer (warp 8, lane 0) ----------------
    if (warp == 8) {
        if (lane == 0) {
            int pg = 0;
            auto push = [&](const unsigned char* src) {
                int slot = pg & 3;
                if (pg >= 4) mbar_wait(SB + OFF_EMPTY + (u32)slot * 8u, ((pg >> 2) - 1) & 1);
                expect_tx(SB + OFF_FULL + (u32)slot * 8u, 32768u);
                bulk_cp(SB + OFF_RING + (u32)slot * 32768u, src, 32768u, SB + OFF_FULL + (u32)slot * 8u);
                pg++;
            };
            for (int t = 0; t < 64; t++)
                for (int c = 0; c < 12; c++) push(g_enc + (size_t)c * 32768);
            for (int t = 0; t < 80; t++) {
                for (int c = 0; c < 10; c++) push(g_ssm + (size_t)c * 32768);
                for (int c = 0; c < 2; c++)  push(g_cw + (size_t)c * 32768);
            }
        }
        return;
    }

    // ---------------- compute warps 0..7 ----------------
    const int gg = lane >> 2, tig = lane & 3;
    float ebias[4], sbias[4], cb[2];
#pragma unroll
    for (int m = 0; m < 2; m++)
#pragma unroll
        for (int rh = 0; rh < 2; rh++) {
            int j = warp * 32 + m * 16 + gg + rh * 8;
            ebias[m * 2 + rh] = b_ih[j] + b_hh[j];
            sbias[m * 2 + rh] = A_b[j] + B_b[j];
        }
    if (warp < 4) { cb[0] = C_b[warp * 16 + gg]; cb[1] = C_b[warp * 16 + gg + 8]; }

    int gch = 0;

    // ================= encoder =================
    for (int t = 0; t < 64; t++) {
        BAR1();
        float acc[2][4][4] = {};
        gemm_main(SB, warp, lane, 12, gch, acc);
        BAR1();
        const bool last = (t == 63);
        const u32 hb = last ? 64u : 128u;      // h base slot in U (ssm vs enc layout)
        const u32 Pb = last ? 640u : 768u;     // part stride bytes
#pragma unroll
        for (int m = 0; m < 2; m++)
#pragma unroll
            for (int nt = 0; nt < 4; nt++)
#pragma unroll
                for (int r = 0; r < 4; r++) {
                    int j = warp * 32 + m * 16 + gg + (r >> 1) * 8;
                    int b = nt * 8 + tig * 2 + (r & 1);
                    float v = my_tanh(acc[m][nt][r] + ebias[m * 2 + (r >> 1)]);
                    put_duo(SB + OFF_U + (u32)b * UP, hb + (u32)j, v, Pb);
                }
        // stage next inputs
        if (!last) {
            int b = tid >> 3, k16 = (tid & 7) * 16;
            const float* s = ((k16 < 64) ? pre_x : pre_y) +
                             (size_t)(t + 1) * 4096 * 64 + (size_t)(bbase + b) * 64 + (k16 & 63);
            u32 ub = SB + OFF_U + (u32)b * UP;
#pragma unroll
            for (int kk = 0; kk < 16; kk++)
                put_duo(ub, (u32)(k16 + kk), s[kk], 768u);
        } else {
            int b = tid >> 3, k16 = (tid & 7) * 16;
            if (k16 < 64) {
                const float* s = fwd_x + (size_t)(bbase + b) * 64 + k16;
                u32 ub = SB + OFF_U + (u32)b * UP;
#pragma unroll
                for (int kk = 0; kk < 16; kk++)
                    put_duo(ub, (u32)(k16 + kk), s[kk], 640u);
            }
        }
    }

    // ================= SSM + output projection =================
    for (int t = 0; t < 80; t++) {
        BAR1();
        float acc[2][4][4] = {};
        gemm_main(SB, warp, lane, 10, gch, acc);
        BAR1();
        // write h_t (ssm layout: h at 64.., parts 0/320)
#pragma unroll
        for (int m = 0; m < 2; m++)
#pragma unroll
            for (int nt = 0; nt < 4; nt++)
#pragma unroll
                for (int r = 0; r < 4; r++) {
                    int j = warp * 32 + m * 16 + gg + (r >> 1) * 8;
                    int b = nt * 8 + tig * 2 + (r & 1);
                    float v = acc[m][nt][r] + sbias[m * 2 + (r >> 1)];
                    put_duo(SB + OFF_U + (u32)b * UP, 64u + (u32)j, v, 640u);
                }
        BAR1();
        // phase 3: warps 0-3 run C projection; warps 4-7 stage x_{t+1} and release chunks
        if (warp < 4) {
            float accc[4][4] = {};
            const u32 bB = SB + OFF_U + (u32)(lane >> 2) * UP + (u32)(lane & 3) * 4u;
            for (int c = 0; c < 2; c++) {
                int slot = gch & 3;
                mbar_wait(SB + OFF_FULL + (u32)slot * 8u, (gch >> 2) & 1);
                u32 ab = SB + OFF_RING + (u32)slot * 32768u + (u32)(warp * 512) + (u32)(lane * 16);
#pragma unroll 4
                for (int sl = 0; sl < 16; sl++) {
                    u32 su = (u32)c * 20u + 4u + (u32)sl;   // U h-region slabs (parts 0/320)
                    u32 a0[4];
                    LDS128U(a0, ab + (u32)sl * 2048u);
                    u32 bk = bB + su * 32u;
#pragma unroll
                    for (int nt = 0; nt < 4; nt++) {
                        u32 b0, b1;
                        LDS32U(b0, bk + (u32)nt * (8u * UP));
                        LDS32U(b1, bk + (u32)nt * (8u * UP) + 16u);
                        MMA16816(accc[nt], a0, b0, b1);
                    }
                }
                __syncwarp();
                if (lane == 0) mbar_arrive(SB + OFF_EMPTY + (u32)slot * 8u);
                gch++;
            }
            // epilogue: y -> gmem
            float* op = out + (size_t)t * 4096 * 64 + (size_t)bbase * 64;
#pragma unroll
            for (int nt = 0; nt < 4; nt++)
#pragma unroll
                for (int r = 0; r < 4; r++) {
                    int o = warp * 16 + gg + (r >> 1) * 8;
                    int b = nt * 8 + tig * 2 + (r & 1);
                    op[(size_t)b * 64 + o] = accc[nt][r] + cb[r >> 1];
                }
        } else {
            if (t < 79) {
                int idx = tid - 128;
                int b = idx >> 2, k16 = (idx & 3) * 16;
                const float* s = fwd_x + (size_t)(t + 1) * 4096 * 64 + (size_t)(bbase + b) * 64 + k16;
                u32 ub = SB + OFF_U + (u32)b * UP;
#pragma unroll
                for (int kk = 0; kk < 16; kk++)
                    put_duo(ub, (u32)(k16 + kk), s[kk], 640u);
            }
            for (int c = 0; c < 2; c++) {
                int slot = gch & 3;
                __syncwarp();
                if (lane == 0) mbar_arrive(SB + OFF_EMPTY + (u32)slot * 8u);
                gch++;
            }
        }
    }
}

extern "C" void kernel_launch(void* const* d_in, const int* in_sizes, int n_in,
                              void* d_out, int out_size) {
    const float* pre_x = (const float*)d_in[0];
    const float* pre_y = (const float*)d_in[1];
    const float* fwd_x = (const float*)d_in[2];
    const float* A_w   = (const float*)d_in[3];
    const float* A_b   = (const float*)d_in[4];
    const float* B_b   = (const float*)d_in[6];
    const float* B_w   = (const float*)d_in[5];
    const float* C_w   = (const float*)d_in[7];
    const float* C_b   = (const float*)d_in[8];
    const float* W_ih  = (const float*)d_in[9];
    const float* b_ih  = (const float*)d_in[10];
    const float* W_hh  = (const float*)d_in[11];
    const float* b_hh  = (const float*)d_in[12];
    float* out = (float*)d_out;

    prep<<<1536, 256>>>(A_w, B_w, C_w, W_ih, W_hh);
    cudaFuncSetAttribute(ss_main, cudaFuncAttributeMaxDynamicSharedMemorySize, SMEM_TOTAL);
    ss_main<<<128, 288, SMEM_TOTAL>>>(pre_x, pre_y, fwd_x, A_b, B_b, C_b,
                                      b_ih, b_hh, out);
}